// round 1
// baseline (speedup 1.0000x reference)
#include <cuda_runtime.h>
#include <math.h>

// Problem constants
#define BDIM 2
#define SDIM 2048
#define HDIM 1024
#define EDIM 8
#define FFDIM 4096
#define NTOK (BDIM*SDIM)     // 4096 tokens
#define NSLOT (NTOK*2)       // 8192 (token, expert) slots
#define LN_EPS 1e-5f

// GEMM tile config
#define BM 128
#define BN 128
#define BK 8
#define NTHR 256

// ---------------- scratch (__device__ globals; no runtime alloc) ----------------
__device__ float g_xhat[(size_t)NTOK*HDIM];          // 16 MB
__device__ float g_act [(size_t)NSLOT*FFDIM];        // 128 MB
__device__ int   g_cnt[EDIM];
__device__ int   g_off[EDIM];
__device__ int   g_e0[NTOK], g_e1[NTOK], g_p0[NTOK], g_p1[NTOK];
__device__ float g_g0[NTOK], g_g1[NTOK];
__device__ int   g_tok[NSLOT];
__device__ float g_gate[NSLOT];

// ---------------- kernel 0: zero counters ----------------
__global__ void k_zero() {
    if (threadIdx.x < EDIM) g_cnt[threadIdx.x] = 0;
}

// ---------------- kernel 1: router + layernorm stats + xhat + out=x ----------------
__global__ __launch_bounds__(NTHR) void k_router(
    const float* __restrict__ x, const float* __restrict__ rW,
    const float* __restrict__ rb, float* __restrict__ out)
{
    int t = blockIdx.x;
    const float* xr = x + (size_t)t*HDIM;

    float s = 0.f, ss = 0.f;
    float lg[EDIM];
#pragma unroll
    for (int e = 0; e < EDIM; e++) lg[e] = 0.f;

    for (int h = threadIdx.x; h < HDIM; h += NTHR) {
        float v = xr[h];
        s += v; ss += v*v;
        const float* w = rW + (size_t)h*EDIM;
#pragma unroll
        for (int e = 0; e < EDIM; e++) lg[e] += v * w[e];
    }

    // warp reduce 10 values
#pragma unroll
    for (int o = 16; o > 0; o >>= 1) {
        s  += __shfl_down_sync(0xffffffffu, s,  o);
        ss += __shfl_down_sync(0xffffffffu, ss, o);
#pragma unroll
        for (int e = 0; e < EDIM; e++) lg[e] += __shfl_down_sync(0xffffffffu, lg[e], o);
    }

    __shared__ float red[NTHR/32][10];
    __shared__ float bc[2];
    int wid = threadIdx.x >> 5, lane = threadIdx.x & 31;
    if (lane == 0) {
        red[wid][0] = s; red[wid][1] = ss;
#pragma unroll
        for (int e = 0; e < EDIM; e++) red[wid][2+e] = lg[e];
    }
    __syncthreads();

    if (threadIdx.x == 0) {
        float S = 0.f, SS = 0.f, L[EDIM];
#pragma unroll
        for (int e = 0; e < EDIM; e++) L[e] = 0.f;
#pragma unroll
        for (int w = 0; w < NTHR/32; w++) {
            S += red[w][0]; SS += red[w][1];
#pragma unroll
            for (int e = 0; e < EDIM; e++) L[e] += red[w][2+e];
        }
        float mu = S / (float)HDIM;
        float var = SS / (float)HDIM - mu*mu;
        float rstd = rsqrtf(var + LN_EPS);
        bc[0] = mu; bc[1] = rstd;

#pragma unroll
        for (int e = 0; e < EDIM; e++) L[e] += rb[e];

        // top-2 (earliest index wins ties, matching jax.lax.top_k)
        int i0 = 0; float l0 = L[0];
#pragma unroll
        for (int e = 1; e < EDIM; e++) if (L[e] > l0) { l0 = L[e]; i0 = e; }
        int i1 = -1; float l1 = -3.4e38f;
#pragma unroll
        for (int e = 0; e < EDIM; e++) if (e != i0 && L[e] > l1) { l1 = L[e]; i1 = e; }

        float ed = expf(l1 - l0);
        float inv = 1.f / (1.f + ed);
        float gg0 = inv, gg1 = ed * inv;

        int p0 = atomicAdd(&g_cnt[i0], 1);
        int p1 = atomicAdd(&g_cnt[i1], 1);
        g_e0[t] = i0; g_e1[t] = i1;
        g_p0[t] = p0; g_p1[t] = p1;
        g_g0[t] = gg0; g_g1[t] = gg1;
    }
    __syncthreads();

    float mu = bc[0], rstd = bc[1];
    for (int h = threadIdx.x; h < HDIM; h += NTHR) {
        float v = xr[h];
        g_xhat[(size_t)t*HDIM + h] = (v - mu) * rstd;
        out[(size_t)t*HDIM + h] = v;   // residual init: out = x + sum(gate*y), sum(gates)=1
    }
}

// ---------------- kernel 2: prefix offsets ----------------
__global__ void k_offsets() {
    if (threadIdx.x == 0) {
        int a = 0;
#pragma unroll
        for (int e = 0; e < EDIM; e++) { g_off[e] = a; a += g_cnt[e]; }
    }
}

// ---------------- kernel 3: scatter tokens into compacted slot lists ----------------
__global__ void k_scatter() {
    int t = blockIdx.x * blockDim.x + threadIdx.x;
    if (t >= NTOK) return;
    int s0 = g_off[g_e0[t]] + g_p0[t];
    g_tok[s0] = t; g_gate[s0] = g_g0[t];
    int s1 = g_off[g_e1[t]] + g_p1[t];
    g_tok[s1] = t; g_gate[s1] = g_g1[t];
}

// ---------------- kernel 4: GEMM1  act = gelu((xhat*g+b) @ W1 + b1) ----------------
__global__ __launch_bounds__(NTHR) void k_gemm1(
    const float* __restrict__ lng, const float* __restrict__ lnb,
    const float* __restrict__ W1, const float* __restrict__ b1)
{
    int e = blockIdx.z;
    int cnt = g_cnt[e];
    int m0 = blockIdx.y * BM;
    if (m0 >= cnt) return;
    int off = g_off[e];
    int n0 = blockIdx.x * BN;

    const float* Bmat = W1 + (size_t)e*HDIM*FFDIM;
    const float* ge = lng + (size_t)e*HDIM;
    const float* be = lnb + (size_t)e*HDIM;

    __shared__ __align__(16) float As[BK][BM];
    __shared__ __align__(16) float Bs[BK][BN];
    __shared__ int toks[BM];

    int tid = threadIdx.x;
    for (int i = tid; i < BM; i += NTHR) {
        int r = m0 + i;
        toks[i] = (r < cnt) ? g_tok[off + r] : g_tok[off];
    }
    __syncthreads();

    int arow = tid >> 1;            // 0..127
    int acol = (tid & 1) * 4;       // 0 or 4
    int brow = tid >> 5;            // 0..7
    int bcol = (tid & 31) * 4;      // 0..124

    int ty = tid >> 4, tx = tid & 15;  // 16 x 16

    float acc[8][8];
#pragma unroll
    for (int i = 0; i < 8; i++)
#pragma unroll
        for (int j = 0; j < 8; j++) acc[i][j] = 0.f;

    const size_t arow_base = (size_t)toks[arow] * HDIM;

    for (int k0 = 0; k0 < HDIM; k0 += BK) {
        float4 xv = *(const float4*)&g_xhat[arow_base + k0 + acol];
        float4 gv = *(const float4*)&ge[k0 + acol];
        float4 bv = *(const float4*)&be[k0 + acol];
        As[acol+0][arow] = xv.x*gv.x + bv.x;
        As[acol+1][arow] = xv.y*gv.y + bv.y;
        As[acol+2][arow] = xv.z*gv.z + bv.z;
        As[acol+3][arow] = xv.w*gv.w + bv.w;
        *(float4*)&Bs[brow][bcol] = *(const float4*)&Bmat[(size_t)(k0+brow)*FFDIM + n0 + bcol];
        __syncthreads();
#pragma unroll
        for (int k = 0; k < BK; k++) {
            float4 a0 = *(const float4*)&As[k][ty*8];
            float4 a1 = *(const float4*)&As[k][ty*8 + 4];
            float4 b0 = *(const float4*)&Bs[k][tx*4];
            float4 b1v = *(const float4*)&Bs[k][64 + tx*4];
            float av[8] = {a0.x,a0.y,a0.z,a0.w,a1.x,a1.y,a1.z,a1.w};
            float bw[8] = {b0.x,b0.y,b0.z,b0.w,b1v.x,b1v.y,b1v.z,b1v.w};
#pragma unroll
            for (int i = 0; i < 8; i++)
#pragma unroll
                for (int j = 0; j < 8; j++) acc[i][j] += av[i]*bw[j];
        }
        __syncthreads();
    }

    // epilogue: + b1, exact gelu, store to act (cols: tx*4 and 64+tx*4 groups)
    const float* b1e = b1 + (size_t)e*FFDIM;
#pragma unroll
    for (int i = 0; i < 8; i++) {
        int r = m0 + ty*8 + i;
        if (r >= cnt) continue;
        size_t rowp = (size_t)(off + r) * FFDIM + n0;
        {
            int c = tx*4;
            float4 v;
            float t0 = acc[i][0] + b1e[n0+c+0]; v.x = 0.5f*t0*(1.f+erff(t0*0.70710678118f));
            float t1 = acc[i][1] + b1e[n0+c+1]; v.y = 0.5f*t1*(1.f+erff(t1*0.70710678118f));
            float t2 = acc[i][2] + b1e[n0+c+2]; v.z = 0.5f*t2*(1.f+erff(t2*0.70710678118f));
            float t3 = acc[i][3] + b1e[n0+c+3]; v.w = 0.5f*t3*(1.f+erff(t3*0.70710678118f));
            *(float4*)&g_act[rowp + c] = v;
        }
        {
            int c = 64 + tx*4;
            float4 v;
            float t0 = acc[i][4] + b1e[n0+c+0]; v.x = 0.5f*t0*(1.f+erff(t0*0.70710678118f));
            float t1 = acc[i][5] + b1e[n0+c+1]; v.y = 0.5f*t1*(1.f+erff(t1*0.70710678118f));
            float t2 = acc[i][6] + b1e[n0+c+2]; v.z = 0.5f*t2*(1.f+erff(t2*0.70710678118f));
            float t3 = acc[i][7] + b1e[n0+c+3]; v.w = 0.5f*t3*(1.f+erff(t3*0.70710678118f));
            *(float4*)&g_act[rowp + c] = v;
        }
    }
}

// ---------------- kernel 5: GEMM2  out += gate * (act @ W2 + b2) ----------------
__global__ __launch_bounds__(NTHR) void k_gemm2(
    const float* __restrict__ W2, const float* __restrict__ b2,
    float* __restrict__ out)
{
    int e = blockIdx.z;
    int cnt = g_cnt[e];
    int m0 = blockIdx.y * BM;
    if (m0 >= cnt) return;
    int off = g_off[e];
    int n0 = blockIdx.x * BN;

    const float* Bmat = W2 + (size_t)e*FFDIM*HDIM;

    __shared__ __align__(16) float As[BK][BM];
    __shared__ __align__(16) float Bs[BK][BN];
    __shared__ int toks[BM];
    __shared__ float gts[BM];

    int tid = threadIdx.x;
    for (int i = tid; i < BM; i += NTHR) {
        int r = m0 + i;
        if (r < cnt) { toks[i] = g_tok[off + r]; gts[i] = g_gate[off + r]; }
        else         { toks[i] = -1;            gts[i] = 0.f; }
    }
    __syncthreads();

    int arow = tid >> 1;
    int acol = (tid & 1) * 4;
    int brow = tid >> 5;
    int bcol = (tid & 31) * 4;
    int ty = tid >> 4, tx = tid & 15;

    int am = m0 + arow;
    size_t aslot = (size_t)(off + (am < cnt ? am : 0)) * FFDIM;

    float acc[8][8];
#pragma unroll
    for (int i = 0; i < 8; i++)
#pragma unroll
        for (int j = 0; j < 8; j++) acc[i][j] = 0.f;

    for (int k0 = 0; k0 < FFDIM; k0 += BK) {
        float4 av = *(const float4*)&g_act[aslot + k0 + acol];
        As[acol+0][arow] = av.x;
        As[acol+1][arow] = av.y;
        As[acol+2][arow] = av.z;
        As[acol+3][arow] = av.w;
        *(float4*)&Bs[brow][bcol] = *(const float4*)&Bmat[(size_t)(k0+brow)*HDIM + n0 + bcol];
        __syncthreads();
#pragma unroll
        for (int k = 0; k < BK; k++) {
            float4 a0 = *(const float4*)&As[k][ty*8];
            float4 a1 = *(const float4*)&As[k][ty*8 + 4];
            float4 b0 = *(const float4*)&Bs[k][tx*4];
            float4 b1v = *(const float4*)&Bs[k][64 + tx*4];
            float avr[8] = {a0.x,a0.y,a0.z,a0.w,a1.x,a1.y,a1.z,a1.w};
            float bw[8] = {b0.x,b0.y,b0.z,b0.w,b1v.x,b1v.y,b1v.z,b1v.w};
#pragma unroll
            for (int i = 0; i < 8; i++)
#pragma unroll
                for (int j = 0; j < 8; j++) acc[i][j] += avr[i]*bw[j];
        }
        __syncthreads();
    }

    const float* b2e = b2 + (size_t)e*HDIM;
#pragma unroll
    for (int i = 0; i < 8; i++) {
        int r = ty*8 + i;
        int tok = toks[r];
        if (m0 + r >= cnt || tok < 0) continue;
        float gate = gts[r];
        size_t orow = (size_t)tok * HDIM + n0;
#pragma unroll
        for (int j = 0; j < 4; j++) {
            int c = tx*4 + j;
            atomicAdd(&out[orow + c], gate * (acc[i][j] + b2e[n0 + c]));
        }
#pragma unroll
        for (int j = 0; j < 4; j++) {
            int c = 64 + tx*4 + j;
            atomicAdd(&out[orow + c], gate * (acc[i][j+4] + b2e[n0 + c]));
        }
    }
}

// ---------------- launch ----------------
extern "C" void kernel_launch(void* const* d_in, const int* in_sizes, int n_in,
                              void* d_out, int out_size)
{
    const float* x   = (const float*)d_in[0];
    const float* rW  = (const float*)d_in[1];
    const float* rb  = (const float*)d_in[2];
    const float* lng = (const float*)d_in[3];
    const float* lnb = (const float*)d_in[4];
    const float* W1  = (const float*)d_in[5];
    const float* b1  = (const float*)d_in[6];
    const float* W2  = (const float*)d_in[7];
    const float* b2  = (const float*)d_in[8];
    float* out = (float*)d_out;

    k_zero<<<1, 32>>>();
    k_router<<<NTOK, NTHR>>>(x, rW, rb, out);
    k_offsets<<<1, 1>>>();
    k_scatter<<<(NTOK + 255)/256, 256>>>();

    dim3 g1(FFDIM/BN, NTOK/BM, EDIM);   // (32, 32, 8), early-exit on count
    k_gemm1<<<g1, NTHR>>>(lng, lnb, W1, b1);

    dim3 g2(HDIM/BN, NTOK/BM, EDIM);    // (8, 32, 8)
    k_gemm2<<<g2, NTHR>>>(W2, b2, out);
}

// round 5
// speedup vs baseline: 1.5624x; 1.5624x over previous
#include <cuda_runtime.h>
#include <cuda_bf16.h>
#include <math.h>
#include <stdint.h>

// Problem constants
#define BDIM 2
#define SDIM 2048
#define HDIM 1024
#define EDIM 8
#define FFDIM 4096
#define NTOK (BDIM*SDIM)     // 4096
#define NSLOT (NTOK*2)       // 8192
#define LN_EPS 1e-5f

// GEMM tile config
#define BM 128
#define BN 128
#define BK 32
#define GTHR 256
#define KSTRIDE 40           // BK + 8 pad (elems) -> 80B row stride, conflict-free ldmatrix

// dynamic smem layout (bytes)
// per stage (x2): AHI 10240 | ALO 10240 | BF32 16384  => 36864
// shared (x1):    BBH 10240 | BBL 10240
#define ST_AHI 0
#define ST_ALO 10240
#define ST_BF32 20480
#define STAGE_BYTES 36864
#define BBH_OFF (2*STAGE_BYTES)
#define BBL_OFF (BBH_OFF + 10240)
#define DSMEM_BYTES (BBL_OFF + 10240)   // 94208

// ---------------- scratch (~144 MiB total, matches R1-passing footprint) ----------------
__device__ __nv_bfloat16 g_xh_hi[(size_t)NTOK*HDIM];       // 8 MiB
__device__ __nv_bfloat16 g_xh_lo[(size_t)NTOK*HDIM];       // 8 MiB
__device__ __nv_bfloat16 g_act_hi[(size_t)NSLOT*FFDIM];    // 64 MiB
__device__ __nv_bfloat16 g_act_lo[(size_t)NSLOT*FFDIM];    // 64 MiB
__device__ float g_bias1p[(size_t)EDIM*FFDIM];             // b1 + ln_b @ W1
__device__ int   g_cnt[EDIM];
__device__ int   g_off[EDIM];
__device__ int   g_e0[NTOK], g_e1[NTOK], g_p0[NTOK], g_p1[NTOK];
__device__ float g_g0[NTOK], g_g1[NTOK];
__device__ int   g_tok[NSLOT];
__device__ float g_gate[NSLOT];

// ---------------- helpers ----------------
__device__ __forceinline__ uint32_t s2u(const void* p) {
    uint32_t a;
    asm("{ .reg .u64 t; cvta.to.shared.u64 t, %1; cvt.u32.u64 %0, t; }" : "=r"(a) : "l"(p));
    return a;
}
__device__ __forceinline__ void cpa16(uint32_t dst, const void* src) {
    asm volatile("cp.async.cg.shared.global [%0], [%1], 16;" :: "r"(dst), "l"(src));
}
__device__ __forceinline__ void cpa_commit() { asm volatile("cp.async.commit_group;" ::: "memory"); }
__device__ __forceinline__ void cpa_wait1()  { asm volatile("cp.async.wait_group 1;" ::: "memory"); }
__device__ __forceinline__ void cpa_wait0()  { asm volatile("cp.async.wait_group 0;" ::: "memory"); }

__device__ __forceinline__ void ldm4(uint32_t& r0, uint32_t& r1, uint32_t& r2, uint32_t& r3, uint32_t a) {
    asm volatile("ldmatrix.sync.aligned.m8n8.x4.shared.b16 {%0,%1,%2,%3}, [%4];"
                 : "=r"(r0), "=r"(r1), "=r"(r2), "=r"(r3) : "r"(a));
}
__device__ __forceinline__ void mma_bf16(float* d, const uint32_t* a, const uint32_t* b) {
    asm volatile("mma.sync.aligned.m16n8k16.row.col.f32.bf16.bf16.f32 "
                 "{%0,%1,%2,%3},{%4,%5,%6,%7},{%8,%9},{%0,%1,%2,%3};"
                 : "+f"(d[0]), "+f"(d[1]), "+f"(d[2]), "+f"(d[3])
                 : "r"(a[0]), "r"(a[1]), "r"(a[2]), "r"(a[3]), "r"(b[0]), "r"(b[1]));
}
__device__ __forceinline__ uint32_t pack_split(float a, float b, uint32_t& lo_out) {
    __nv_bfloat16 ha = __float2bfloat16(a);
    __nv_bfloat16 hb = __float2bfloat16(b);
    __nv_bfloat16 la = __float2bfloat16(a - __bfloat162float(ha));
    __nv_bfloat16 lb = __float2bfloat16(b - __bfloat162float(hb));
    lo_out = (uint32_t)__bfloat16_as_ushort(la) | ((uint32_t)__bfloat16_as_ushort(lb) << 16);
    return (uint32_t)__bfloat16_as_ushort(ha) | ((uint32_t)__bfloat16_as_ushort(hb) << 16);
}

// ---------------- kernel: zero counters ----------------
__global__ void k_zero() { if (threadIdx.x < EDIM) g_cnt[threadIdx.x] = 0; }

// ---------------- kernel: router + LN + xhat split + out=x ----------------
__global__ __launch_bounds__(256) void k_router(
    const float* __restrict__ x, const float* __restrict__ rW,
    const float* __restrict__ rb, float* __restrict__ out)
{
    int t = blockIdx.x;
    const float* xr = x + (size_t)t*HDIM;

    float s = 0.f, ss = 0.f;
    float lg[EDIM];
#pragma unroll
    for (int e = 0; e < EDIM; e++) lg[e] = 0.f;

    for (int h = threadIdx.x; h < HDIM; h += 256) {
        float v = xr[h];
        s += v; ss += v*v;
        const float* w = rW + (size_t)h*EDIM;
#pragma unroll
        for (int e = 0; e < EDIM; e++) lg[e] += v * w[e];
    }
#pragma unroll
    for (int o = 16; o > 0; o >>= 1) {
        s  += __shfl_down_sync(0xffffffffu, s,  o);
        ss += __shfl_down_sync(0xffffffffu, ss, o);
#pragma unroll
        for (int e = 0; e < EDIM; e++) lg[e] += __shfl_down_sync(0xffffffffu, lg[e], o);
    }
    __shared__ float red[8][10];
    __shared__ float bc[2];
    int wid = threadIdx.x >> 5, lane = threadIdx.x & 31;
    if (lane == 0) {
        red[wid][0] = s; red[wid][1] = ss;
#pragma unroll
        for (int e = 0; e < EDIM; e++) red[wid][2+e] = lg[e];
    }
    __syncthreads();
    if (threadIdx.x == 0) {
        float S = 0.f, SS = 0.f, L[EDIM];
#pragma unroll
        for (int e = 0; e < EDIM; e++) L[e] = 0.f;
#pragma unroll
        for (int w = 0; w < 8; w++) {
            S += red[w][0]; SS += red[w][1];
#pragma unroll
            for (int e = 0; e < EDIM; e++) L[e] += red[w][2+e];
        }
        float mu = S / (float)HDIM;
        float var = SS / (float)HDIM - mu*mu;
        float rstd = rsqrtf(var + LN_EPS);
        bc[0] = mu; bc[1] = rstd;
#pragma unroll
        for (int e = 0; e < EDIM; e++) L[e] += rb[e];
        int i0 = 0; float l0 = L[0];
#pragma unroll
        for (int e = 1; e < EDIM; e++) if (L[e] > l0) { l0 = L[e]; i0 = e; }
        int i1 = -1; float l1 = -3.4e38f;
#pragma unroll
        for (int e = 0; e < EDIM; e++) if (e != i0 && L[e] > l1) { l1 = L[e]; i1 = e; }
        float ed = expf(l1 - l0);
        float inv = 1.f / (1.f + ed);
        int p0 = atomicAdd(&g_cnt[i0], 1);
        int p1 = atomicAdd(&g_cnt[i1], 1);
        g_e0[t] = i0; g_e1[t] = i1;
        g_p0[t] = p0; g_p1[t] = p1;
        g_g0[t] = inv; g_g1[t] = ed * inv;
    }
    __syncthreads();
    float mu = bc[0], rstd = bc[1];
    for (int h = threadIdx.x; h < HDIM; h += 256) {
        float xv = xr[h];
        float v = (xv - mu) * rstd;
        __nv_bfloat16 hi = __float2bfloat16(v);
        __nv_bfloat16 lo = __float2bfloat16(v - __bfloat162float(hi));
        g_xh_hi[(size_t)t*HDIM + h] = hi;
        g_xh_lo[(size_t)t*HDIM + h] = lo;
        out[(size_t)t*HDIM + h] = xv;   // residual init: out = x + sum(gate*y), sum(gates)=1
    }
}

// ---------------- kernel: prefix offsets ----------------
__global__ void k_offsets() {
    if (threadIdx.x == 0) {
        int a = 0;
#pragma unroll
        for (int e = 0; e < EDIM; e++) { g_off[e] = a; a += g_cnt[e]; }
    }
}

// ---------------- kernel: scatter ----------------
__global__ void k_scatter() {
    int t = blockIdx.x * blockDim.x + threadIdx.x;
    if (t >= NTOK) return;
    int s0 = g_off[g_e0[t]] + g_p0[t];
    int s1 = g_off[g_e1[t]] + g_p1[t];
    g_tok[s0] = t; g_gate[s0] = g_g0[t];
    g_tok[s1] = t; g_gate[s1] = g_g1[t];
}

// ---------------- kernel: bias1' = b1 + ln_b @ W1 ----------------
__global__ __launch_bounds__(256) void k_bias1(
    const float* __restrict__ W1, const float* __restrict__ b1,
    const float* __restrict__ lnb)
{
    int e = blockIdx.y;
    int n = blockIdx.x * 256 + threadIdx.x;
    float acc = b1[(size_t)e*FFDIM + n];
    const float* Wp = W1 + (size_t)e*HDIM*FFDIM + n;
    const float* bp = lnb + (size_t)e*HDIM;
    for (int k = 0; k < HDIM; k++)
        acc += bp[k] * Wp[(size_t)k*FFDIM];
    g_bias1p[(size_t)e*FFDIM + n] = acc;
}

// ---------------- shared GEMM building blocks ----------------
// Load B fp32 tile [BK=32][BN=128] (natural [k][n] layout) via cp.async.
// W element [k][n] at Wp byte offset ((k)*Nd + n)*4.
__device__ __forceinline__ void loadB_f32(uint32_t stB, const char* Wp,
                                          int k0, int n0, int Nd, int tid)
{
    int row = tid >> 3;                 // 0..31
    int cb  = (tid & 7) * 16;           // 0..112
#pragma unroll
    for (int q = 0; q < 4; q++) {
        int colb = cb + q * 128;        // 0..504 (bytes); 512 B per row
        size_t src = ((size_t)(k0 + row) * Nd + n0) * 4 + colb;
        cpa16(stB + (uint32_t)row * 512 + colb, Wp + src);
    }
}

// Convert fp32 smem tile [k][n] -> bf16 hi/lo smem [n][KSTRIDE] (optional per-k scale).
__device__ __forceinline__ void convB(const float* bf32, char* bbh, char* bbl,
                                      const float* scale_k, int tid)
{
#pragma unroll
    for (int p = 0; p < 2; p++) {
        int slot = tid + p * 256;       // 0..511
        int n  = slot & 127;
        int kg = slot >> 7;             // 0..3 -> k = kg*8 .. kg*8+7
        float v[8];
#pragma unroll
        for (int i = 0; i < 8; i++) {
            float w = bf32[(kg*8 + i) * BN + n];
            if (scale_k) w *= scale_k[kg*8 + i];
            v[i] = w;
        }
        uint32_t off = (uint32_t)n * (KSTRIDE*2) + kg * 16;
#pragma unroll
        for (int j = 0; j < 4; j++) {
            uint32_t lo;
            uint32_t hi = pack_split(v[j*2], v[j*2+1], lo);
            *(uint32_t*)(bbh + off + j*4) = hi;
            *(uint32_t*)(bbl + off + j*4) = lo;
        }
    }
}

// ---------------- GEMM1: act = gelu(xhat @ (g.W1) + bias1') ----------------
__global__ __launch_bounds__(GTHR, 1) void k_gemm1(
    const float* __restrict__ W1, const float* __restrict__ lng)
{
    int e = blockIdx.z;
    int cnt = g_cnt[e];
    int m0 = blockIdx.y * BM;
    if (m0 >= cnt) return;
    int off = g_off[e];
    int n0 = blockIdx.x * BN;

    extern __shared__ char db[];
    __shared__ int toks[BM];

    int tid = threadIdx.x;
    int wid = tid >> 5, lane = tid & 31;
    int m_warp = (wid & 1) * 64;
    int n_warp = (wid >> 1) * 32;

    for (int i = tid; i < BM; i += GTHR) {
        int r = m0 + i;
        toks[i] = g_tok[off + (r < cnt ? r : 0)];
    }
    __syncthreads();

    const char* Wp = (const char*)(W1 + (size_t)e*HDIM*FFDIM);
    const float* ge = lng + (size_t)e*HDIM;

    uint32_t sb = s2u(db);
    int lrow = tid >> 2;                // 0..63
    int lq   = (tid & 3) * 16;          // byte quarter within 64B

    auto load_chunk = [&](int c, int buf) {
        uint32_t st = sb + buf * STAGE_BYTES;
        int k0 = c * BK;
#pragma unroll
        for (int p = 0; p < 2; p++) {
            int row = lrow + p * 64;
            uint32_t so = (uint32_t)row * (KSTRIDE*2) + lq;
            size_t ga = ((size_t)toks[row] * HDIM + k0) * 2 + lq;
            cpa16(st + ST_AHI + so, (const char*)g_xh_hi + ga);
            cpa16(st + ST_ALO + so, (const char*)g_xh_lo + ga);
        }
        loadB_f32(st + ST_BF32, Wp, k0, n0, FFDIM, tid);
    };

    float acc[4][4][4];
#pragma unroll
    for (int a = 0; a < 4; a++)
#pragma unroll
        for (int b = 0; b < 4; b++)
#pragma unroll
            for (int c = 0; c < 4; c++) acc[a][b][c] = 0.f;

    int li = lane & 7, ls = lane >> 3;
    int arow = (ls & 1) * 8 + li;
    int acolb = (ls >> 1) * 8;
    int brow = (ls >> 1) * 8 + li;
    int bcolb = (ls & 1) * 8;

    const int NC = HDIM / BK;   // 32
    load_chunk(0, 0);
    cpa_commit();

    for (int c = 0; c < NC; c++) {
        if (c + 1 < NC) { load_chunk(c+1, (c+1)&1); cpa_commit(); cpa_wait1(); }
        else cpa_wait0();
        __syncthreads();
        uint32_t st = sb + (c & 1) * STAGE_BYTES;
        convB((const float*)(db + (c & 1) * STAGE_BYTES + ST_BF32),
              db + BBH_OFF, db + BBL_OFF, ge + c * BK, tid);
        __syncthreads();
#pragma unroll
        for (int ks = 0; ks < 2; ks++) {
            uint32_t ah[4][4], al[4][4];
#pragma unroll
            for (int mt = 0; mt < 4; mt++) {
                uint32_t ao = (uint32_t)(m_warp + mt*16 + arow) * (KSTRIDE*2) + (ks*16 + acolb)*2;
                ldm4(ah[mt][0], ah[mt][1], ah[mt][2], ah[mt][3], st + ST_AHI + ao);
                ldm4(al[mt][0], al[mt][1], al[mt][2], al[mt][3], st + ST_ALO + ao);
            }
            uint32_t bh[4][2], bl[4][2];
#pragma unroll
            for (int np = 0; np < 2; np++) {
                uint32_t bo = (uint32_t)(n_warp + np*16 + brow) * (KSTRIDE*2) + (ks*16 + bcolb)*2;
                uint32_t r0, r1, r2, r3;
                ldm4(r0, r1, r2, r3, sb + BBH_OFF + bo);
                bh[np*2][0] = r0; bh[np*2][1] = r1; bh[np*2+1][0] = r2; bh[np*2+1][1] = r3;
                ldm4(r0, r1, r2, r3, sb + BBL_OFF + bo);
                bl[np*2][0] = r0; bl[np*2][1] = r1; bl[np*2+1][0] = r2; bl[np*2+1][1] = r3;
            }
#pragma unroll
            for (int mt = 0; mt < 4; mt++)
#pragma unroll
                for (int nt = 0; nt < 4; nt++) {
                    mma_bf16(acc[mt][nt], ah[mt], bh[nt]);
                    mma_bf16(acc[mt][nt], ah[mt], bl[nt]);
                    mma_bf16(acc[mt][nt], al[mt], bh[nt]);
                }
        }
        __syncthreads();
    }

    // epilogue: + bias1', gelu, split, store bf16 hi/lo
    int grp = lane >> 2, tig = lane & 3;
    const float* bp = g_bias1p + (size_t)e*FFDIM;
#pragma unroll
    for (int mt = 0; mt < 4; mt++) {
#pragma unroll
        for (int half = 0; half < 2; half++) {
            int rloc = m_warp + mt*16 + grp + half*8;
            int rg = m0 + rloc;
            if (rg >= cnt) continue;
            size_t orow = (size_t)(off + rg) * FFDIM;
#pragma unroll
            for (int nt = 0; nt < 4; nt++) {
                int col = n0 + n_warp + nt*8 + tig*2;
                float v0 = acc[mt][nt][half*2+0] + bp[col];
                float v1 = acc[mt][nt][half*2+1] + bp[col+1];
                v0 = 0.5f*v0*(1.f + erff(v0*0.70710678118654752f));
                v1 = 0.5f*v1*(1.f + erff(v1*0.70710678118654752f));
                uint32_t lo;
                uint32_t hi = pack_split(v0, v1, lo);
                *(uint32_t*)(g_act_hi + orow + col) = hi;
                *(uint32_t*)(g_act_lo + orow + col) = lo;
            }
        }
    }
}

// ---------------- GEMM2: out += gate * (act @ W2 + b2) ----------------
__global__ __launch_bounds__(GTHR, 1) void k_gemm2(
    const float* __restrict__ W2, const float* __restrict__ b2,
    float* __restrict__ out)
{
    int e = blockIdx.z;
    int cnt = g_cnt[e];
    int m0 = blockIdx.y * BM;
    if (m0 >= cnt) return;
    int off = g_off[e];
    int n0 = blockIdx.x * BN;

    extern __shared__ char db[];
    __shared__ int toks[BM];
    __shared__ float gts[BM];

    int tid = threadIdx.x;
    int wid = tid >> 5, lane = tid & 31;
    int m_warp = (wid & 1) * 64;
    int n_warp = (wid >> 1) * 32;

    for (int i = tid; i < BM; i += GTHR) {
        int r = m0 + i;
        if (r < cnt) { toks[i] = g_tok[off + r]; gts[i] = g_gate[off + r]; }
        else         { toks[i] = -1;            gts[i] = 0.f; }
    }
    __syncthreads();

    const char* Wp = (const char*)(W2 + (size_t)e*FFDIM*HDIM);

    uint32_t sb = s2u(db);
    int lrow = tid >> 2;
    int lq   = (tid & 3) * 16;

    auto load_chunk = [&](int c, int buf) {
        uint32_t st = sb + buf * STAGE_BYTES;
        int k0 = c * BK;
#pragma unroll
        for (int p = 0; p < 2; p++) {
            int row = lrow + p * 64;
            int rr = m0 + row;
            size_t slot = (size_t)(off + (rr < cnt ? rr : 0));
            uint32_t so = (uint32_t)row * (KSTRIDE*2) + lq;
            size_t ga = (slot * FFDIM + k0) * 2 + lq;
            cpa16(st + ST_AHI + so, (const char*)g_act_hi + ga);
            cpa16(st + ST_ALO + so, (const char*)g_act_lo + ga);
        }
        loadB_f32(st + ST_BF32, Wp, k0, n0, HDIM, tid);
    };

    float acc[4][4][4];
#pragma unroll
    for (int a = 0; a < 4; a++)
#pragma unroll
        for (int b = 0; b < 4; b++)
#pragma unroll
            for (int c = 0; c < 4; c++) acc[a][b][c] = 0.f;

    int li = lane & 7, ls = lane >> 3;
    int arow = (ls & 1) * 8 + li;
    int acolb = (ls >> 1) * 8;
    int brow = (ls >> 1) * 8 + li;
    int bcolb = (ls & 1) * 8;

    const int NC = FFDIM / BK;   // 128
    load_chunk(0, 0);
    cpa_commit();

    for (int c = 0; c < NC; c++) {
        if (c + 1 < NC) { load_chunk(c+1, (c+1)&1); cpa_commit(); cpa_wait1(); }
        else cpa_wait0();
        __syncthreads();
        uint32_t st = sb + (c & 1) * STAGE_BYTES;
        convB((const float*)(db + (c & 1) * STAGE_BYTES + ST_BF32),
              db + BBH_OFF, db + BBL_OFF, (const float*)nullptr, tid);
        __syncthreads();
#pragma unroll
        for (int ks = 0; ks < 2; ks++) {
            uint32_t ah[4][4], al[4][4];
#pragma unroll
            for (int mt = 0; mt < 4; mt++) {
                uint32_t ao = (uint32_t)(m_warp + mt*16 + arow) * (KSTRIDE*2) + (ks*16 + acolb)*2;
                ldm4(ah[mt][0], ah[mt][1], ah[mt][2], ah[mt][3], st + ST_AHI + ao);
                ldm4(al[mt][0], al[mt][1], al[mt][2], al[mt][3], st + ST_ALO + ao);
            }
            uint32_t bh[4][2], bl[4][2];
#pragma unroll
            for (int np = 0; np < 2; np++) {
                uint32_t bo = (uint32_t)(n_warp + np*16 + brow) * (KSTRIDE*2) + (ks*16 + bcolb)*2;
                uint32_t r0, r1, r2, r3;
                ldm4(r0, r1, r2, r3, sb + BBH_OFF + bo);
                bh[np*2][0] = r0; bh[np*2][1] = r1; bh[np*2+1][0] = r2; bh[np*2+1][1] = r3;
                ldm4(r0, r1, r2, r3, sb + BBL_OFF + bo);
                bl[np*2][0] = r0; bl[np*2][1] = r1; bl[np*2+1][0] = r2; bl[np*2+1][1] = r3;
            }
#pragma unroll
            for (int mt = 0; mt < 4; mt++)
#pragma unroll
                for (int nt = 0; nt < 4; nt++) {
                    mma_bf16(acc[mt][nt], ah[mt], bh[nt]);
                    mma_bf16(acc[mt][nt], ah[mt], bl[nt]);
                    mma_bf16(acc[mt][nt], al[mt], bh[nt]);
                }
        }
        __syncthreads();
    }

    // epilogue: out[tok] += gate * (acc + b2)
    int grp = lane >> 2, tig = lane & 3;
    const float* bp = b2 + (size_t)e*HDIM;
#pragma unroll
    for (int mt = 0; mt < 4; mt++) {
#pragma unroll
        for (int half = 0; half < 2; half++) {
            int rloc = m_warp + mt*16 + grp + half*8;
            int rg = m0 + rloc;
            if (rg >= cnt) continue;
            int tok = toks[rloc];
            float gate = gts[rloc];
            size_t orow = (size_t)tok * HDIM;
#pragma unroll
            for (int nt = 0; nt < 4; nt++) {
                int col = n0 + n_warp + nt*8 + tig*2;
                atomicAdd(&out[orow + col],     gate * (acc[mt][nt][half*2+0] + bp[col]));
                atomicAdd(&out[orow + col + 1], gate * (acc[mt][nt][half*2+1] + bp[col+1]));
            }
        }
    }
}

// ---------------- launch ----------------
extern "C" void kernel_launch(void* const* d_in, const int* in_sizes, int n_in,
                              void* d_out, int out_size)
{
    const float* x   = (const float*)d_in[0];
    const float* rW  = (const float*)d_in[1];
    const float* rb  = (const float*)d_in[2];
    const float* lng = (const float*)d_in[3];
    const float* lnb = (const float*)d_in[4];
    const float* W1  = (const float*)d_in[5];
    const float* b1  = (const float*)d_in[6];
    const float* W2  = (const float*)d_in[7];
    const float* b2  = (const float*)d_in[8];
    float* out = (float*)d_out;

    cudaFuncSetAttribute(k_gemm1, cudaFuncAttributeMaxDynamicSharedMemorySize, DSMEM_BYTES);
    cudaFuncSetAttribute(k_gemm2, cudaFuncAttributeMaxDynamicSharedMemorySize, DSMEM_BYTES);

    k_zero<<<1, 32>>>();
    k_router<<<NTOK, 256>>>(x, rW, rb, out);
    k_offsets<<<1, 1>>>();
    k_scatter<<<(NTOK + 255)/256, 256>>>();

    // bias1' = b1 + ln_b @ W1
    dim3 gb1(FFDIM/256, EDIM);
    k_bias1<<<gb1, 256>>>(W1, b1, lnb);

    dim3 g1(FFDIM/BN, NSLOT/BM, EDIM);   // (32, 64, 8), early-exit on count
    k_gemm1<<<g1, GTHR, DSMEM_BYTES>>>(W1, lng);

    dim3 g2(HDIM/BN, NSLOT/BM, EDIM);    // (8, 64, 8)
    k_gemm2<<<g2, GTHR, DSMEM_BYTES>>>(W2, b2, out);
}